// round 2
// baseline (speedup 1.0000x reference)
#include <cuda_runtime.h>
#include <cstdint>

#define N_TOK 8192
#define CDIM  1024
#define HDIM  4096
#define NEXP  8
#define BM    128
#define BN    128
#define BK    16
#define AST   20    // A smem row stride (floats), conflict-free for frag reads
#define BST   136   // B smem row stride (floats), conflict-free for frag reads
#define MAXTILES 80

// ---- scratch (static __device__ — allocation-free per harness rules) ----
__device__ float g_h[(size_t)N_TOK * HDIM];   // fc1 activations, sorted order
__device__ int   g_idx[N_TOK];
__device__ float g_prob[N_TOK];
__device__ int   g_perm[N_TOK];               // sorted pos -> token id
__device__ int   g_counts[NEXP];
__device__ int   g_cursor[NEXP];
__device__ int   g_offset[NEXP + 1];
__device__ int   g_tileExpert[MAXTILES];
__device__ int   g_tileStart[MAXTILES];
__device__ int   g_tileCount[MAXTILES];
__device__ int   g_numTiles;

// ---------------------------------------------------------------- helpers
__device__ __forceinline__ uint32_t f2tf(float f) {
    uint32_t r;
    asm("cvt.rna.tf32.f32 %0, %1;" : "=r"(r) : "f"(f));
    return r;
}
__device__ __forceinline__ float gelu_f(float v) {
    return 0.5f * v * (1.0f + erff(v * 0.70710678118654752f));
}
__device__ __forceinline__ void cp16(uint32_t dst, const void* src, bool pred) {
    int sz = pred ? 16 : 0;  // src-size 0 => zero-fill 16B
    asm volatile("cp.async.ca.shared.global [%0], [%1], 16, %2;\n"
                 :: "r"(dst), "l"(src), "r"(sz));
}

// ---------------------------------------------------------------- kernels
__global__ void init_k() {
    int t = threadIdx.x;
    if (t < NEXP) { g_counts[t] = 0; g_cursor[t] = 0; }
}

// one warp per token: logits = x @ Wr + br; softmax; top-1
__global__ void router_k(const float* __restrict__ x,
                         const float* __restrict__ Wr,
                         const float* __restrict__ br) {
    int gt  = blockIdx.x * blockDim.x + threadIdx.x;
    int tok = gt >> 5;
    int lane = gt & 31;
    if (tok >= N_TOK) return;
    const float* xr = x + (size_t)tok * CDIM;
    float s[NEXP];
#pragma unroll
    for (int e = 0; e < NEXP; e++) s[e] = 0.f;
    for (int k = lane; k < CDIM; k += 32) {
        float xv = xr[k];
        const float4* w = (const float4*)(Wr + (size_t)k * NEXP);
        float4 w0 = w[0], w1 = w[1];
        s[0] += xv * w0.x; s[1] += xv * w0.y; s[2] += xv * w0.z; s[3] += xv * w0.w;
        s[4] += xv * w1.x; s[5] += xv * w1.y; s[6] += xv * w1.z; s[7] += xv * w1.w;
    }
#pragma unroll
    for (int e = 0; e < NEXP; e++) {
#pragma unroll
        for (int o = 16; o > 0; o >>= 1)
            s[e] += __shfl_xor_sync(0xffffffffu, s[e], o);
    }
    if (lane == 0) {
        float l[NEXP];
        l[0] = s[0] + br[0];
        float m = l[0]; int mi = 0;
#pragma unroll
        for (int e = 1; e < NEXP; e++) {
            l[e] = s[e] + br[e];
            if (l[e] > m) { m = l[e]; mi = e; }   // first max on ties (matches argmax)
        }
        float sum = 0.f;
#pragma unroll
        for (int e = 0; e < NEXP; e++) sum += expf(l[e] - m);
        g_prob[tok] = 1.0f / sum;   // softmax value at the max logit
        g_idx[tok]  = mi;
        atomicAdd(&g_counts[mi], 1);
    }
}

// serial tiny setup: offsets, tile table, aux loss
__global__ void setup_k(float* out, int out_size) {
    if (threadIdx.x != 0 || blockIdx.x != 0) return;
    int off = 0, nt = 0;
    for (int e = 0; e < NEXP; e++) {
        g_offset[e] = off;
        int c = g_counts[e];
        int t = (c + BM - 1) / BM;
        for (int i = 0; i < t; i++) {
            g_tileExpert[nt] = e;
            g_tileStart[nt]  = off + i * BM;
            int rem = c - i * BM;
            g_tileCount[nt]  = rem < BM ? rem : BM;
            nt++;
        }
        off += c;
    }
    g_offset[NEXP] = off;
    g_numTiles = nt;
    float aux = 0.f;
    float tot = (float)off;
    if (tot < 1.f) tot = 1.f;
    for (int e = 0; e < NEXP; e++) {
        float d = (float)g_counts[e] / tot - 1.0f / NEXP;
        aux += d * d;
    }
    aux *= 1.0f / NEXP;
    if (out_size > N_TOK * CDIM) out[(size_t)N_TOK * CDIM] = aux;
}

__global__ void scatter_k() {
    int t = blockIdx.x * blockDim.x + threadIdx.x;
    if (t >= N_TOK) return;
    int e = g_idx[t];
    int p = atomicAdd(&g_cursor[e], 1);
    g_perm[g_offset[e] + p] = t;
}

// Grouped GEMM: MODE 0: h = gelu(x[perm] @ W1[e] + b1[e])   (K=CDIM, NDIM=HDIM)
//               MODE 1: out[token] = prob * (h @ W2[e] + b2[e]) (K=HDIM, NDIM=CDIM)
template <int MODE>
__global__ void __launch_bounds__(256, 1)
moe_gemm_k(const float* __restrict__ Xin, const float* __restrict__ W,
           const float* __restrict__ bias, float* __restrict__ OutG,
           int K, int NDIM) {
    __shared__ float As[2][BM][AST];
    __shared__ float Bs[2][BK][BST];

    int mt = blockIdx.x;
    if (mt >= g_numTiles) return;
    int e      = g_tileExpert[mt];
    int gstart = g_tileStart[mt];
    int mcount = g_tileCount[mt];
    int n0     = blockIdx.y * BN;

    const float* We = W + (size_t)e * K * NDIM;

    int tid  = threadIdx.x;
    int lane = tid & 31;
    int warp = tid >> 5;
    int wm   = warp & 3;     // 4 warps along M (32 rows each)
    int wn   = warp >> 2;    // 2 warps along N (64 cols each)

    // ---- A gather: each thread owns 2 rows, one 16B chunk per row per step
    int ra = tid >> 2;            // 0..63
    int rb = ra + 64;
    int ac = (tid & 3) * 4;       // float offset in BK chunk
    bool va = ra < mcount, vb = rb < mcount;
    const float* pa;
    const float* pb;
    if (MODE == 0) {
        int t0 = va ? g_perm[gstart + ra] : 0;
        int t1 = vb ? g_perm[gstart + rb] : 0;
        pa = Xin + (size_t)t0 * K + ac;
        pb = Xin + (size_t)t1 * K + ac;
    } else {
        int r0c = va ? (gstart + ra) : 0;
        int r1c = vb ? (gstart + rb) : 0;
        pa = g_h + (size_t)r0c * K + ac;
        pb = g_h + (size_t)r1c * K + ac;
    }

    // ---- B: 16 rows x 128 cols per step; each thread 2 x 16B
    int brw = tid >> 5;           // 0..7
    int bc  = (tid & 31) * 4;
    const float* pB0 = We + (size_t)brw * NDIM + n0 + bc;
    const float* pB1 = We + (size_t)(brw + 8) * NDIM + n0 + bc;

    uint32_t sAa[2], sAb[2], sB0[2], sB1[2];
#pragma unroll
    for (int st = 0; st < 2; st++) {
        sAa[st] = (uint32_t)__cvta_generic_to_shared(&As[st][ra][ac]);
        sAb[st] = (uint32_t)__cvta_generic_to_shared(&As[st][rb][ac]);
        sB0[st] = (uint32_t)__cvta_generic_to_shared(&Bs[st][brw][bc]);
        sB1[st] = (uint32_t)__cvta_generic_to_shared(&Bs[st][brw + 8][bc]);
    }

    float c[2][8][4];
#pragma unroll
    for (int mi = 0; mi < 2; mi++)
#pragma unroll
        for (int ni = 0; ni < 8; ni++)
#pragma unroll
            for (int j = 0; j < 4; j++) c[mi][ni][j] = 0.f;

    int nsteps = K / BK;

    // prefetch step 0
    cp16(sAa[0], pa, va);
    cp16(sAb[0], pb, vb);
    cp16(sB0[0], pB0, true);
    cp16(sB1[0], pB1, true);
    asm volatile("cp.async.commit_group;\n" ::: "memory");

    int gid = lane >> 2;   // 0..7
    int tig = lane & 3;    // 0..3

    for (int s = 0; s < nsteps; s++) {
        if (s + 1 < nsteps) {
            int st = (s + 1) & 1;
            int k0 = (s + 1) * BK;
            cp16(sAa[st], pa + k0, va);
            cp16(sAb[st], pb + k0, vb);
            cp16(sB0[st], pB0 + (size_t)k0 * NDIM, true);
            cp16(sB1[st], pB1 + (size_t)k0 * NDIM, true);
            asm volatile("cp.async.commit_group;\n" ::: "memory");
            asm volatile("cp.async.wait_group 1;\n" ::: "memory");
        } else {
            asm volatile("cp.async.wait_group 0;\n" ::: "memory");
        }
        __syncthreads();
        int st = s & 1;
#pragma unroll
        for (int kk = 0; kk < 2; kk++) {
            int kb = kk * 8;
            uint32_t a[2][4];
#pragma unroll
            for (int mi = 0; mi < 2; mi++) {
                int r0 = wm * 32 + mi * 16 + gid;
                a[mi][0] = f2tf(As[st][r0][kb + tig]);
                a[mi][1] = f2tf(As[st][r0 + 8][kb + tig]);
                a[mi][2] = f2tf(As[st][r0][kb + tig + 4]);
                a[mi][3] = f2tf(As[st][r0 + 8][kb + tig + 4]);
            }
            uint32_t b[8][2];
#pragma unroll
            for (int ni = 0; ni < 8; ni++) {
                int nn = wn * 64 + ni * 8 + gid;
                b[ni][0] = f2tf(Bs[st][kb + tig][nn]);
                b[ni][1] = f2tf(Bs[st][kb + tig + 4][nn]);
            }
#pragma unroll
            for (int mi = 0; mi < 2; mi++)
#pragma unroll
                for (int ni = 0; ni < 8; ni++) {
                    asm volatile(
                        "mma.sync.aligned.m16n8k8.row.col.f32.tf32.tf32.f32 "
                        "{%0,%1,%2,%3}, {%4,%5,%6,%7}, {%8,%9}, {%0,%1,%2,%3};\n"
                        : "+f"(c[mi][ni][0]), "+f"(c[mi][ni][1]),
                          "+f"(c[mi][ni][2]), "+f"(c[mi][ni][3])
                        : "r"(a[mi][0]), "r"(a[mi][1]), "r"(a[mi][2]), "r"(a[mi][3]),
                          "r"(b[ni][0]), "r"(b[ni][1]));
                }
        }
        __syncthreads();
    }

    // ---- epilogue
#pragma unroll
    for (int mi = 0; mi < 2; mi++) {
        int rlo = wm * 32 + mi * 16 + gid;
        int rhi = rlo + 8;
        bool vlo = rlo < mcount, vhi = rhi < mcount;
        size_t dlo = 0, dhi = 0;
        float glo = 1.f, ghi = 1.f;
        if (MODE == 0) {
            dlo = (size_t)(gstart + rlo) * NDIM;
            dhi = (size_t)(gstart + rhi) * NDIM;
        } else {
            int tlo = vlo ? g_perm[gstart + rlo] : 0;
            int thi = vhi ? g_perm[gstart + rhi] : 0;
            glo = g_prob[tlo];
            ghi = g_prob[thi];
            dlo = (size_t)tlo * NDIM;
            dhi = (size_t)thi * NDIM;
        }
#pragma unroll
        for (int ni = 0; ni < 8; ni++) {
            int col = n0 + wn * 64 + ni * 8 + tig * 2;
            float bz0 = bias[(size_t)e * NDIM + col];
            float bz1 = bias[(size_t)e * NDIM + col + 1];
            float v00 = c[mi][ni][0] + bz0, v01 = c[mi][ni][1] + bz1;  // row rlo
            float v10 = c[mi][ni][2] + bz0, v11 = c[mi][ni][3] + bz1;  // row rhi
            if (MODE == 0) {
                if (vlo) *(float2*)&g_h[dlo + col] = make_float2(gelu_f(v00), gelu_f(v01));
                if (vhi) *(float2*)&g_h[dhi + col] = make_float2(gelu_f(v10), gelu_f(v11));
            } else {
                if (vlo) *(float2*)&OutG[dlo + col] = make_float2(glo * v00, glo * v01);
                if (vhi) *(float2*)&OutG[dhi + col] = make_float2(ghi * v10, ghi * v11);
            }
        }
    }
}

// ---------------------------------------------------------------- launch
extern "C" void kernel_launch(void* const* d_in, const int* in_sizes, int n_in,
                              void* d_out, int out_size) {
    const float* x  = (const float*)d_in[0];
    const float* Wr = (const float*)d_in[1];
    const float* br = (const float*)d_in[2];
    const float* W1 = (const float*)d_in[3];
    const float* b1 = (const float*)d_in[4];
    const float* W2 = (const float*)d_in[5];
    const float* b2 = (const float*)d_in[6];
    float* out = (float*)d_out;

    init_k<<<1, 32>>>();
    router_k<<<N_TOK * 32 / 256, 256>>>(x, Wr, br);
    setup_k<<<1, 32>>>(out, out_size);
    scatter_k<<<N_TOK / 256, 256>>>();
    // max M-tiles: sum_e ceil(cnt_e/128) <= 64 + 7 = 71 -> grid.x = 72
    moe_gemm_k<0><<<dim3(72, HDIM / BN), 256>>>(x,       W1, b1, nullptr, CDIM, HDIM);
    moe_gemm_k<1><<<dim3(72, CDIM / BN), 256>>>(nullptr, W2, b2, out,     HDIM, CDIM);
}